// round 3
// baseline (speedup 1.0000x reference)
#include <cuda_runtime.h>
#include <cuda_bf16.h>

#define BT 64
#define CH 256
#define HH 64
#define WW 64
#define JJ 17
#define NP 4
#define NPTS (BT * JJ)

// uniform 4-way select (index is block-uniform)
__device__ __forceinline__ float sel4(float4 q, int i) {
    float r = q.x;
    if (i == 1) r = q.y;
    else if (i == 2) r = q.z;
    else if (i == 3) r = q.w;
    return r;
}
__device__ __forceinline__ float pick5(float4 q, float e, int i) {
    return (i == 4) ? e : sel4(q, i);
}

// Full gather fallback (rare)
__device__ __forceinline__ float sample_bilinear_c(
    const float* __restrict__ plane, float gx, float gy)
{
    float x = (gx + 1.0f) * 0.5f * (float)(WW - 1);
    float y = (gy + 1.0f) * 0.5f * (float)(HH - 1);
    float x0f = floorf(x), y0f = floorf(y);
    float wx1 = x - x0f, wx0 = 1.0f - wx1;
    float wy1 = y - y0f, wy0 = 1.0f - wy1;
    int x0 = (int)x0f, y0 = (int)y0f;
    int x1 = x0 + 1,   y1 = y0 + 1;

    float vx0 = (x0 >= 0 && x0 <= WW - 1) ? 1.0f : 0.0f;
    float vx1 = (x1 >= 0 && x1 <= WW - 1) ? 1.0f : 0.0f;
    float vy0 = (y0 >= 0 && y0 <= HH - 1) ? 1.0f : 0.0f;
    float vy1 = (y1 >= 0 && y1 <= HH - 1) ? 1.0f : 0.0f;

    int xc0 = min(max(x0, 0), WW - 1);
    int xc1 = min(max(x1, 0), WW - 1);
    int yc0 = min(max(y0, 0), HH - 1);
    int yc1 = min(max(y1, 0), HH - 1);

    const float* r0 = plane + yc0 * WW;
    const float* r1 = plane + yc1 * WW;
    float v00 = __ldg(r0 + xc0);
    float v01 = __ldg(r0 + xc1);
    float v10 = __ldg(r1 + xc0);
    float v11 = __ldg(r1 + xc1);

    return v00 * (wx0 * wy0 * vx0 * vy0)
         + v01 * (wx1 * wy0 * vx1 * vy0)
         + v10 * (wx0 * wy1 * vx0 * vy1)
         + v11 * (wx1 * wy1 * vx1 * vy1);
}

__global__ __launch_bounds__(256)
void fused_kernel(const float* __restrict__ feat, const float* __restrict__ kp,
                  const float* __restrict__ w1, const float* __restrict__ b1,
                  const float* __restrict__ w2, const float* __restrict__ b2,
                  float* __restrict__ out)
{
    __shared__ float s_seed[CH];      // 1 KB
    __shared__ float s_part[256];     // 1 KB
    __shared__ float s_h[128];        // 0.5 KB
    __shared__ float s_grid[2 * NP];  // 8 deformed coords

    const int pt  = blockIdx.x;
    const int tid = threadIdx.x;
    const int c   = tid;
    const int b   = pt / JJ;

    const float gx = __ldg(kp + pt * 2 + 0);
    const float gy = __ldg(kp + pt * 2 + 1);

    // ---------- Stage A: seed sample + register window ----------
    float x = (gx + 1.0f) * 0.5f * (float)(WW - 1);
    float y = (gy + 1.0f) * 0.5f * (float)(HH - 1);
    float x0f = floorf(x), y0f = floorf(y);
    float wx1 = x - x0f, wx0 = 1.0f - wx1;
    float wy1 = y - y0f, wy0 = 1.0f - wy1;
    int x0 = (int)x0f, y0 = (int)y0f;
    int x1 = x0 + 1,   y1 = y0 + 1;

    float vx0 = (x0 >= 0 && x0 <= WW - 1) ? 1.0f : 0.0f;
    float vx1 = (x1 >= 0 && x1 <= WW - 1) ? 1.0f : 0.0f;
    float vy0 = (y0 >= 0 && y0 <= HH - 1) ? 1.0f : 0.0f;
    float vy1 = (y1 >= 0 && y1 <= HH - 1) ? 1.0f : 0.0f;

    const int syc0 = min(max(y0, 0), HH - 1);
    const int syc1 = min(max(y1, 0), HH - 1);
    const int xc0s = min(max(x0, 0), WW - 1);
    const int xc1s = min(max(x1, 0), WW - 1);
    const int sbc  = xc0s & ~3;
    const int o0   = xc0s - sbc;
    const int o1   = xc1s - sbc;
    const bool have_e = (o1 == 4);

    const float* plane = feat + ((size_t)b * CH + c) * (HH * WW);
    const float* r0 = plane + syc0 * WW;
    const float* r1 = plane + syc1 * WW;
    float4 q0 = __ldg((const float4*)(r0 + sbc));
    float4 q1 = __ldg((const float4*)(r1 + sbc));
    float e0 = 0.0f, e1 = 0.0f;
    if (have_e) {            // block-uniform
        e0 = __ldg(r0 + xc1s);
        e1 = __ldg(r1 + xc1s);
    }

    {
        float v00 = sel4(q0, o0);
        float v01 = have_e ? e0 : sel4(q0, o1);
        float v10 = sel4(q1, o0);
        float v11 = have_e ? e1 : sel4(q1, o1);
        s_seed[c] = v00 * (wx0 * wy0 * vx0 * vy0)
                  + v01 * (wx1 * wy0 * vx1 * vy0)
                  + v10 * (wx0 * wy1 * vx0 * vy1)
                  + v11 * (wx1 * wy1 * vx1 * vy1);
    }
    __syncthreads();

    // ---------- Stage B1: layer 1 (256->128, relu), 2 threads per output ----------
    {
        const int o    = tid & 127;
        const int half = tid >> 7;
        const float4* wrow = (const float4*)w1 + o * (CH / 4) + half * 32;
        const float4* srow = (const float4*)s_seed + half * 32;
        float a = 0.0f;
        #pragma unroll 8
        for (int c4 = 0; c4 < 32; c4++) {
            float4 w = __ldg(wrow + c4);
            float4 s = srow[c4];
            a += w.x * s.x + w.y * s.y + w.z * s.z + w.w * s.w;
        }
        s_part[tid] = a;
    }
    __syncthreads();
    if (tid < 128)
        s_h[tid] = fmaxf(s_part[tid] + s_part[tid + 128] + __ldg(b1 + tid), 0.0f);
    __syncthreads();

    // ---------- Stage B2: layer 2 (128->8) + grid ----------
    if (tid < 64) {
        const int oo = tid >> 3;   // output 0..7  (= n*2 + d)
        const int j  = tid & 7;    // k-slice
        const float4* w2r = (const float4*)w2 + oo * 32 + j * 4;
        const float4* hr  = (const float4*)s_h + j * 4;
        float a = 0.0f;
        #pragma unroll
        for (int i = 0; i < 4; i++) {
            float4 w = __ldg(w2r + i);
            float4 h = hr[i];
            a += w.x * h.x + w.y * h.y + w.z * h.z + w.w * h.w;
        }
        a += __shfl_down_sync(0xffffffff, a, 4);
        a += __shfl_down_sync(0xffffffff, a, 2);
        a += __shfl_down_sync(0xffffffff, a, 1);
        if (j == 0) {
            a += __ldg(b2 + oo);
            int d = oo & 1;
            float scale = (d == 0) ? (2.0f / (WW - 1)) : (2.0f / (HH - 1));
            float base  = (d == 0) ? gx : gy;
            s_grid[oo] = base + a * scale;
        }
    }
    __syncthreads();

    // ---------- Stage C: deformable resample from register window ----------
    float* obase = out + (size_t)pt * (NP * CH) + c;
    #pragma unroll
    for (int n = 0; n < NP; n++) {
        float dgx = s_grid[n * 2 + 0];
        float dgy = s_grid[n * 2 + 1];

        float xx = (dgx + 1.0f) * 0.5f * (float)(WW - 1);
        float yy = (dgy + 1.0f) * 0.5f * (float)(HH - 1);
        float xf = floorf(xx), yf = floorf(yy);
        float ax1 = xx - xf, ax0 = 1.0f - ax1;
        float ay1 = yy - yf, ay0 = 1.0f - ay1;
        int dx0 = (int)xf, dy0 = (int)yf;
        int dx1 = dx0 + 1, dy1 = dy0 + 1;

        float ux0 = (dx0 >= 0 && dx0 <= WW - 1) ? 1.0f : 0.0f;
        float ux1 = (dx1 >= 0 && dx1 <= WW - 1) ? 1.0f : 0.0f;
        float uy0 = (dy0 >= 0 && dy0 <= HH - 1) ? 1.0f : 0.0f;
        float uy1 = (dy1 >= 0 && dy1 <= HH - 1) ? 1.0f : 0.0f;

        int cx0 = min(max(dx0, 0), WW - 1);
        int cx1 = min(max(dx1, 0), WW - 1);
        int cy0 = min(max(dy0, 0), HH - 1);
        int cy1 = min(max(dy1, 0), HH - 1);

        int i0 = cx0 - sbc;
        int i1 = cx1 - sbc;
        int ilim = have_e ? 4 : 3;
        bool fast = (cy0 == syc0 || cy0 == syc1)
                 && (cy1 == syc0 || cy1 == syc1)
                 && (i0 >= 0) && (i1 <= ilim);

        float r;
        if (fast) {   // block-uniform branch
            float4 ra = (cy0 == syc0) ? q0 : q1;
            float4 rb = (cy1 == syc0) ? q0 : q1;
            float ea  = (cy0 == syc0) ? e0 : e1;
            float eb  = (cy1 == syc0) ? e0 : e1;
            float v00 = pick5(ra, ea, i0);
            float v01 = pick5(ra, ea, i1);
            float v10 = pick5(rb, eb, i0);
            float v11 = pick5(rb, eb, i1);
            r = v00 * (ax0 * ay0 * ux0 * uy0)
              + v01 * (ax1 * ay0 * ux1 * uy0)
              + v10 * (ax0 * ay1 * ux0 * uy1)
              + v11 * (ax1 * ay1 * ux1 * uy1);
        } else {
            r = sample_bilinear_c(plane, dgx, dgy);
        }
        obase[n * CH] = r;
    }
}

extern "C" void kernel_launch(void* const* d_in, const int* in_sizes, int n_in,
                              void* d_out, int out_size)
{
    const float* feat = (const float*)d_in[0];   // [64,256,64,64]
    const float* kp   = (const float*)d_in[1];   // [64,17,2]
    const float* w1   = (const float*)d_in[2];   // [128,256]
    const float* b1   = (const float*)d_in[3];   // [128]
    const float* w2   = (const float*)d_in[4];   // [8,128]
    const float* b2   = (const float*)d_in[5];   // [8]
    float* out = (float*)d_out;                  // [64,17,1024]

    fused_kernel<<<NPTS, 256>>>(feat, kp, w1, b1, w2, b2, out);
}

// round 4
// speedup vs baseline: 1.4054x; 1.4054x over previous
#include <cuda_runtime.h>
#include <cuda_bf16.h>

#define BT 64
#define CH 256
#define HH 64
#define WW 64
#define JJ 17
#define NP 4
#define NPTS (BT * JJ)

// Scratch: cached 2x4(+edge) corner windows per (pt, channel)
__device__ float4 g_win4[NPTS * CH * 2];  // [pt][c][row0,row1]
__device__ float2 g_wine[NPTS * CH];      // [pt][c][e0,e1] (5th column when needed)

// block-uniform geometry for one keypoint
struct Geom {
    int yc0, yc1, bc, o0, o1;
    bool have_e;
    float w00, w01, w10, w11;   // bilinear weights * validity
};

__device__ __forceinline__ Geom make_geom(float gx, float gy) {
    Geom g;
    float x = (gx + 1.0f) * 0.5f * (float)(WW - 1);
    float y = (gy + 1.0f) * 0.5f * (float)(HH - 1);
    float x0f = floorf(x), y0f = floorf(y);
    float wx1 = x - x0f, wx0 = 1.0f - wx1;
    float wy1 = y - y0f, wy0 = 1.0f - wy1;
    int x0 = (int)x0f, y0 = (int)y0f;
    int x1 = x0 + 1,   y1 = y0 + 1;
    float vx0 = (x0 >= 0 && x0 <= WW - 1) ? 1.0f : 0.0f;
    float vx1 = (x1 >= 0 && x1 <= WW - 1) ? 1.0f : 0.0f;
    float vy0 = (y0 >= 0 && y0 <= HH - 1) ? 1.0f : 0.0f;
    float vy1 = (y1 >= 0 && y1 <= HH - 1) ? 1.0f : 0.0f;
    int xc0 = min(max(x0, 0), WW - 1);
    int xc1 = min(max(x1, 0), WW - 1);
    g.yc0 = min(max(y0, 0), HH - 1);
    g.yc1 = min(max(y1, 0), HH - 1);
    g.bc  = xc0 & ~3;
    g.o0  = xc0 - g.bc;
    g.o1  = xc1 - g.bc;
    g.have_e = (g.o1 == 4);
    g.w00 = wx0 * wy0 * vx0 * vy0;
    g.w01 = wx1 * wy0 * vx1 * vy0;
    g.w10 = wx0 * wy1 * vx0 * vy1;
    g.w11 = wx1 * wy1 * vx1 * vy1;
    return g;
}

__device__ __forceinline__ float sel4(float4 q, int i) {
    float r = q.x;
    if (i == 1) r = q.y;
    else if (i == 2) r = q.z;
    else if (i == 3) r = q.w;
    return r;
}
__device__ __forceinline__ float pick5(float4 q, float e, int i) {
    return (i == 4) ? e : sel4(q, i);
}

// Full gather fallback (rare)
__device__ __forceinline__ float sample_bilinear_c(
    const float* __restrict__ plane, float gx, float gy)
{
    float x = (gx + 1.0f) * 0.5f * (float)(WW - 1);
    float y = (gy + 1.0f) * 0.5f * (float)(HH - 1);
    float x0f = floorf(x), y0f = floorf(y);
    float wx1 = x - x0f, wx0 = 1.0f - wx1;
    float wy1 = y - y0f, wy0 = 1.0f - wy1;
    int x0 = (int)x0f, y0 = (int)y0f;
    int x1 = x0 + 1,   y1 = y0 + 1;
    float vx0 = (x0 >= 0 && x0 <= WW - 1) ? 1.0f : 0.0f;
    float vx1 = (x1 >= 0 && x1 <= WW - 1) ? 1.0f : 0.0f;
    float vy0 = (y0 >= 0 && y0 <= HH - 1) ? 1.0f : 0.0f;
    float vy1 = (y1 >= 0 && y1 <= HH - 1) ? 1.0f : 0.0f;
    int xc0 = min(max(x0, 0), WW - 1);
    int xc1 = min(max(x1, 0), WW - 1);
    int yc0 = min(max(y0, 0), HH - 1);
    int yc1 = min(max(y1, 0), HH - 1);
    const float* r0 = plane + yc0 * WW;
    const float* r1 = plane + yc1 * WW;
    float v00 = __ldg(r0 + xc0);
    float v01 = __ldg(r0 + xc1);
    float v10 = __ldg(r1 + xc0);
    float v11 = __ldg(r1 + xc1);
    return v00 * (wx0 * wy0 * vx0 * vy0)
         + v01 * (wx1 * wy0 * vx1 * vy0)
         + v10 * (wx0 * wy1 * vx0 * vy1)
         + v11 * (wx1 * wy1 * vx1 * vy1);
}

// ───────────────────────── K0: pure window gather ─────────────────────────
// 544 blocks x 256 threads, 2 points/block (MLP>=4 loads/thread).
__global__ __launch_bounds__(256)
void k0_win(const float* __restrict__ feat, const float* __restrict__ kp)
{
    const int c = threadIdx.x;
    #pragma unroll
    for (int p = 0; p < 2; p++) {
        const int pt = blockIdx.x * 2 + p;
        const int b  = pt / JJ;
        const float gx = __ldg(kp + pt * 2 + 0);
        const float gy = __ldg(kp + pt * 2 + 1);
        Geom g = make_geom(gx, gy);

        const float* plane = feat + ((size_t)b * CH + c) * (HH * WW);
        const float* r0 = plane + g.yc0 * WW;
        const float* r1 = plane + g.yc1 * WW;
        float4 q0 = __ldg((const float4*)(r0 + g.bc));
        float4 q1 = __ldg((const float4*)(r1 + g.bc));
        float2 ee = make_float2(0.0f, 0.0f);
        if (g.have_e) {                      // block-uniform
            ee.x = __ldg(r0 + g.bc + 4);
            ee.y = __ldg(r1 + g.bc + 4);
        }
        const size_t wi = (size_t)pt * CH + c;
        g_win4[wi * 2 + 0] = q0;
        g_win4[wi * 2 + 1] = q1;
        g_wine[wi] = ee;
    }
}

// ───────────────── K12: seed-from-window + MLP + resample ─────────────────
// 272 blocks x 256 threads, 4 points/block.
__global__ __launch_bounds__(256)
void k12(const float* __restrict__ feat, const float* __restrict__ kp,
         const float* __restrict__ w1, const float* __restrict__ b1,
         const float* __restrict__ w2, const float* __restrict__ b2,
         float* __restrict__ out)
{
    __shared__ float4 s_seed4[4][CH / 4];   // 4 KB
    __shared__ float4 s_h4[4][32];          // 2 KB
    __shared__ float  s_grid[4][2 * NP];

    const int tid = threadIdx.x;
    const int c   = tid;

    float4 q0[4], q1[4];
    float2 ee[4];
    int   yc0[4], yc1[4], bcc[4];
    bool  he[4];

    // ---- Stage A: load windows, reconstruct seed features ----
    #pragma unroll
    for (int p = 0; p < 4; p++) {
        const int pt = blockIdx.x * 4 + p;
        const float gx = __ldg(kp + pt * 2 + 0);
        const float gy = __ldg(kp + pt * 2 + 1);
        Geom g = make_geom(gx, gy);
        yc0[p] = g.yc0; yc1[p] = g.yc1; bcc[p] = g.bc; he[p] = g.have_e;

        const size_t wi = (size_t)pt * CH + c;
        q0[p] = g_win4[wi * 2 + 0];
        q1[p] = g_win4[wi * 2 + 1];
        ee[p] = g_wine[wi];

        float v00 = sel4(q0[p], g.o0);
        float v01 = pick5(q0[p], ee[p].x, g.o1);
        float v10 = sel4(q1[p], g.o0);
        float v11 = pick5(q1[p], ee[p].y, g.o1);
        ((float*)s_seed4[p])[c] = v00 * g.w00 + v01 * g.w01
                                + v10 * g.w10 + v11 * g.w11;
    }
    __syncthreads();

    // ---- Stage B1: layer 1 (256->128, relu). Warp-coalesced w1 + shfl dot ----
    {
        const int warp = tid >> 5, lane = tid & 31;
        #pragma unroll 4
        for (int oi = 0; oi < 16; oi++) {
            const int o = warp * 16 + oi;
            const float4* row = (const float4*)(w1 + o * CH);
            float4 v0 = __ldg(row + lane);
            float4 v1 = __ldg(row + lane + 32);
            #pragma unroll
            for (int p = 0; p < 4; p++) {
                float4 s0 = s_seed4[p][lane];
                float4 s1 = s_seed4[p][lane + 32];
                float a = v0.x * s0.x + v0.y * s0.y + v0.z * s0.z + v0.w * s0.w
                        + v1.x * s1.x + v1.y * s1.y + v1.z * s1.z + v1.w * s1.w;
                a += __shfl_down_sync(0xffffffffu, a, 16);
                a += __shfl_down_sync(0xffffffffu, a, 8);
                a += __shfl_down_sync(0xffffffffu, a, 4);
                a += __shfl_down_sync(0xffffffffu, a, 2);
                a += __shfl_down_sync(0xffffffffu, a, 1);
                if (lane == 0)
                    ((float*)s_h4[p])[o] = fmaxf(a + __ldg(b1 + o), 0.0f);
            }
        }
    }
    __syncthreads();

    // ---- Stage B2: layer 2 (128->8) + grid. 4p x 8oo x 8j = 256 threads ----
    {
        const int p  = tid >> 6;
        const int r  = tid & 63;
        const int oo = r >> 3;       // output (= n*2 + d)
        const int j  = r & 7;        // k-slice
        const float4* w2r = (const float4*)w2 + oo * 32 + j * 4;
        const float4* hr  = s_h4[p] + j * 4;
        float a = 0.0f;
        #pragma unroll
        for (int i = 0; i < 4; i++) {
            float4 w = __ldg(w2r + i);
            float4 h = hr[i];
            a += w.x * h.x + w.y * h.y + w.z * h.z + w.w * h.w;
        }
        a += __shfl_down_sync(0xffffffffu, a, 4, 8);
        a += __shfl_down_sync(0xffffffffu, a, 2, 8);
        a += __shfl_down_sync(0xffffffffu, a, 1, 8);
        if (j == 0) {
            const int pt = blockIdx.x * 4 + p;
            a += __ldg(b2 + oo);
            int d = oo & 1;
            float scale = (d == 0) ? (2.0f / (WW - 1)) : (2.0f / (HH - 1));
            float base  = __ldg(kp + pt * 2 + d);
            s_grid[p][oo] = base + a * scale;
        }
    }
    __syncthreads();

    // ---- Stage C: deformable resample from register windows ----
    #pragma unroll
    for (int p = 0; p < 4; p++) {
        const int pt = blockIdx.x * 4 + p;
        const int b  = pt / JJ;
        const float* plane = feat + ((size_t)b * CH + c) * (HH * WW);
        float* obase = out + (size_t)pt * (NP * CH) + c;
        const int ilim = he[p] ? 4 : 3;

        #pragma unroll
        for (int n = 0; n < NP; n++) {
            float dgx = s_grid[p][n * 2 + 0];
            float dgy = s_grid[p][n * 2 + 1];

            float xx = (dgx + 1.0f) * 0.5f * (float)(WW - 1);
            float yy = (dgy + 1.0f) * 0.5f * (float)(HH - 1);
            float xf = floorf(xx), yf = floorf(yy);
            float ax1 = xx - xf, ax0 = 1.0f - ax1;
            float ay1 = yy - yf, ay0 = 1.0f - ay1;
            int dx0 = (int)xf, dy0 = (int)yf;
            int dx1 = dx0 + 1, dy1 = dy0 + 1;

            float ux0 = (dx0 >= 0 && dx0 <= WW - 1) ? 1.0f : 0.0f;
            float ux1 = (dx1 >= 0 && dx1 <= WW - 1) ? 1.0f : 0.0f;
            float uy0 = (dy0 >= 0 && dy0 <= HH - 1) ? 1.0f : 0.0f;
            float uy1 = (dy1 >= 0 && dy1 <= HH - 1) ? 1.0f : 0.0f;

            int cx0 = min(max(dx0, 0), WW - 1);
            int cx1 = min(max(dx1, 0), WW - 1);
            int cy0 = min(max(dy0, 0), HH - 1);
            int cy1 = min(max(dy1, 0), HH - 1);

            int i0 = cx0 - bcc[p];
            int i1 = cx1 - bcc[p];
            bool fast = (cy0 == yc0[p] || cy0 == yc1[p])
                     && (cy1 == yc0[p] || cy1 == yc1[p])
                     && (i0 >= 0) && (i1 <= ilim);

            float r;
            if (fast) {                         // block-uniform branch
                float4 ra = (cy0 == yc0[p]) ? q0[p] : q1[p];
                float4 rb = (cy1 == yc0[p]) ? q0[p] : q1[p];
                float ea  = (cy0 == yc0[p]) ? ee[p].x : ee[p].y;
                float eb  = (cy1 == yc0[p]) ? ee[p].x : ee[p].y;
                float v00 = pick5(ra, ea, i0);
                float v01 = pick5(ra, ea, i1);
                float v10 = pick5(rb, eb, i0);
                float v11 = pick5(rb, eb, i1);
                r = v00 * (ax0 * ay0 * ux0 * uy0)
                  + v01 * (ax1 * ay0 * ux1 * uy0)
                  + v10 * (ax0 * ay1 * ux0 * uy1)
                  + v11 * (ax1 * ay1 * ux1 * uy1);
            } else {
                r = sample_bilinear_c(plane, dgx, dgy);
            }
            obase[n * CH] = r;
        }
    }
}

extern "C" void kernel_launch(void* const* d_in, const int* in_sizes, int n_in,
                              void* d_out, int out_size)
{
    const float* feat = (const float*)d_in[0];   // [64,256,64,64]
    const float* kp   = (const float*)d_in[1];   // [64,17,2]
    const float* w1   = (const float*)d_in[2];   // [128,256]
    const float* b1   = (const float*)d_in[3];   // [128]
    const float* w2   = (const float*)d_in[4];   // [8,128]
    const float* b2   = (const float*)d_in[5];   // [8]
    float* out = (float*)d_out;                  // [64,17,1024]

    k0_win<<<NPTS / 2, 256>>>(feat, kp);
    k12<<<NPTS / 4, 256>>>(feat, kp, w1, b1, w2, b2, out);
}

// round 5
// speedup vs baseline: 1.5854x; 1.1280x over previous
#include <cuda_runtime.h>
#include <cuda_bf16.h>

#define BT 64
#define CH 256
#define HH 64
#define WW 64
#define JJ 17
#define NP 4
#define NPTS (BT * JJ)

// Scratch
__device__ float4 g_win4[NPTS * CH * 2];  // [pt][c][row0,row1]
__device__ float2 g_wine[NPTS * CH];      // [pt][c][e0,e1]
__device__ float  g_grid[NPTS * 2 * NP];  // [pt][n*2+d]

struct Geom {
    int yc0, yc1, bc, o0, o1;
    bool have_e;
    float w00, w01, w10, w11;
};

__device__ __forceinline__ Geom make_geom(float gx, float gy) {
    Geom g;
    float x = (gx + 1.0f) * 0.5f * (float)(WW - 1);
    float y = (gy + 1.0f) * 0.5f * (float)(HH - 1);
    float x0f = floorf(x), y0f = floorf(y);
    float wx1 = x - x0f, wx0 = 1.0f - wx1;
    float wy1 = y - y0f, wy0 = 1.0f - wy1;
    int x0 = (int)x0f, y0 = (int)y0f;
    int x1 = x0 + 1,   y1 = y0 + 1;
    float vx0 = (x0 >= 0 && x0 <= WW - 1) ? 1.0f : 0.0f;
    float vx1 = (x1 >= 0 && x1 <= WW - 1) ? 1.0f : 0.0f;
    float vy0 = (y0 >= 0 && y0 <= HH - 1) ? 1.0f : 0.0f;
    float vy1 = (y1 >= 0 && y1 <= HH - 1) ? 1.0f : 0.0f;
    int xc0 = min(max(x0, 0), WW - 1);
    int xc1 = min(max(x1, 0), WW - 1);
    g.yc0 = min(max(y0, 0), HH - 1);
    g.yc1 = min(max(y1, 0), HH - 1);
    g.bc  = xc0 & ~3;
    g.o0  = xc0 - g.bc;
    g.o1  = xc1 - g.bc;
    g.have_e = (g.o1 == 4);
    g.w00 = wx0 * wy0 * vx0 * vy0;
    g.w01 = wx1 * wy0 * vx1 * vy0;
    g.w10 = wx0 * wy1 * vx0 * vy1;
    g.w11 = wx1 * wy1 * vx1 * vy1;
    return g;
}

__device__ __forceinline__ float sel4(float4 q, int i) {
    float r = q.x;
    if (i == 1) r = q.y;
    else if (i == 2) r = q.z;
    else if (i == 3) r = q.w;
    return r;
}
__device__ __forceinline__ float pick5(float4 q, float e, int i) {
    return (i == 4) ? e : sel4(q, i);
}

__device__ __forceinline__ float sample_bilinear_c(
    const float* __restrict__ plane, float gx, float gy)
{
    float x = (gx + 1.0f) * 0.5f * (float)(WW - 1);
    float y = (gy + 1.0f) * 0.5f * (float)(HH - 1);
    float x0f = floorf(x), y0f = floorf(y);
    float wx1 = x - x0f, wx0 = 1.0f - wx1;
    float wy1 = y - y0f, wy0 = 1.0f - wy1;
    int x0 = (int)x0f, y0 = (int)y0f;
    int x1 = x0 + 1,   y1 = y0 + 1;
    float vx0 = (x0 >= 0 && x0 <= WW - 1) ? 1.0f : 0.0f;
    float vx1 = (x1 >= 0 && x1 <= WW - 1) ? 1.0f : 0.0f;
    float vy0 = (y0 >= 0 && y0 <= HH - 1) ? 1.0f : 0.0f;
    float vy1 = (y1 >= 0 && y1 <= HH - 1) ? 1.0f : 0.0f;
    int xc0 = min(max(x0, 0), WW - 1);
    int xc1 = min(max(x1, 0), WW - 1);
    int yc0 = min(max(y0, 0), HH - 1);
    int yc1 = min(max(y1, 0), HH - 1);
    const float* r0 = plane + yc0 * WW;
    const float* r1 = plane + yc1 * WW;
    float v00 = __ldg(r0 + xc0);
    float v01 = __ldg(r0 + xc1);
    float v10 = __ldg(r1 + xc0);
    float v11 = __ldg(r1 + xc1);
    return v00 * (wx0 * wy0 * vx0 * vy0)
         + v01 * (wx1 * wy0 * vx1 * vy0)
         + v10 * (wx0 * wy1 * vx0 * vy1)
         + v11 * (wx1 * wy1 * vx1 * vy1);
}

// ───────────── K0: pure window gather (544 blocks x 256) ─────────────
__global__ __launch_bounds__(256)
void k0_win(const float* __restrict__ feat, const float* __restrict__ kp)
{
    const int c = threadIdx.x;
    #pragma unroll
    for (int p = 0; p < 2; p++) {
        const int pt = blockIdx.x * 2 + p;
        const int b  = pt / JJ;
        const float gx = __ldg(kp + pt * 2 + 0);
        const float gy = __ldg(kp + pt * 2 + 1);
        Geom g = make_geom(gx, gy);

        const float* plane = feat + ((size_t)b * CH + c) * (HH * WW);
        const float* r0 = plane + g.yc0 * WW;
        const float* r1 = plane + g.yc1 * WW;
        float4 q0 = __ldg((const float4*)(r0 + g.bc));
        float4 q1 = __ldg((const float4*)(r1 + g.bc));
        float2 ee = make_float2(0.0f, 0.0f);
        if (g.have_e) {
            ee.x = __ldg(r0 + g.bc + 4);
            ee.y = __ldg(r1 + g.bc + 4);
        }
        const size_t wi = (size_t)pt * CH + c;
        g_win4[wi * 2 + 0] = q0;
        g_win4[wi * 2 + 1] = q1;
        g_wine[wi] = ee;
    }
}

// ───────────── K1: MLP via smem-staged w1 GEMM (272 blocks x 256) ─────────────
#define KT 64                    // channels per w1 tile
__global__ __launch_bounds__(256)
void k1_mlp(const float* __restrict__ kp,
            const float* __restrict__ w1, const float* __restrict__ b1,
            const float* __restrict__ w2, const float* __restrict__ b2)
{
    __shared__ float s_w1t[KT][129];        // transposed tile [k][o], padded
    __shared__ __align__(16) float s_seed[4][CH];   // 4 KB
    __shared__ float s_part[2][128][4];     // 4 KB
    __shared__ __align__(16) float s_h[4][128];     // 2 KB

    const int tid = threadIdx.x;
    const int c   = tid;

    // ---- Stage A: seeds from cached windows ----
    #pragma unroll
    for (int p = 0; p < 4; p++) {
        const int pt = blockIdx.x * 4 + p;
        const float gx = __ldg(kp + pt * 2 + 0);
        const float gy = __ldg(kp + pt * 2 + 1);
        Geom g = make_geom(gx, gy);
        const size_t wi = (size_t)pt * CH + c;
        float4 q0 = g_win4[wi * 2 + 0];
        float4 q1 = g_win4[wi * 2 + 1];
        float2 ee = g_wine[wi];
        float v00 = sel4(q0, g.o0);
        float v01 = pick5(q0, ee.x, g.o1);
        float v10 = sel4(q1, g.o0);
        float v11 = pick5(q1, ee.y, g.o1);
        s_seed[p][c] = v00 * g.w00 + v01 * g.w01 + v10 * g.w10 + v11 * g.w11;
    }

    // ---- Stage B1: layer 1 GEMM (256->128, relu) ----
    const int o = tid & 127;
    const int h = tid >> 7;
    float acc[4] = {0.0f, 0.0f, 0.0f, 0.0f};

    for (int t = 0; t < CH / KT; t++) {
        __syncthreads();
        // load w1 tile [128 out x 64 ch] transposed into smem (coalesced gmem)
        #pragma unroll
        for (int j = 0; j < 8; j++) {
            int L  = tid + j * 256;          // 0..2047 float4s
            int oo = L >> 4;                 // output row
            int k4 = L & 15;                 // float4 within tile row
            float4 v = __ldg((const float4*)(w1 + oo * CH + t * KT) + k4);
            s_w1t[k4 * 4 + 0][oo] = v.x;
            s_w1t[k4 * 4 + 1][oo] = v.y;
            s_w1t[k4 * 4 + 2][oo] = v.z;
            s_w1t[k4 * 4 + 3][oo] = v.w;
        }
        __syncthreads();

        #pragma unroll
        for (int kb = 0; kb < 4; kb++) {     // 8 channels per chunk
            float wv[8];
            #pragma unroll
            for (int u = 0; u < 8; u++)
                wv[u] = s_w1t[h * 32 + kb * 8 + u][o];
            const int ch = t * KT + h * 32 + kb * 8;
            #pragma unroll
            for (int p = 0; p < 4; p++) {
                float4 sa = *(const float4*)&s_seed[p][ch];
                float4 sb = *(const float4*)&s_seed[p][ch + 4];
                acc[p] += wv[0] * sa.x + wv[1] * sa.y + wv[2] * sa.z + wv[3] * sa.w
                        + wv[4] * sb.x + wv[5] * sb.y + wv[6] * sb.z + wv[7] * sb.w;
            }
        }
    }
    #pragma unroll
    for (int p = 0; p < 4; p++) s_part[h][o][p] = acc[p];
    __syncthreads();

    if (tid < 128) {
        float bias = __ldg(b1 + tid);
        #pragma unroll
        for (int p = 0; p < 4; p++)
            s_h[p][tid] = fmaxf(s_part[0][tid][p] + s_part[1][tid][p] + bias, 0.0f);
    }
    __syncthreads();

    // ---- Stage B2: layer 2 (128->8) + grid ----
    {
        const int p  = tid >> 6;
        const int r  = tid & 63;
        const int oo = r >> 3;
        const int j  = r & 7;
        const float4* w2r = (const float4*)w2 + oo * 32 + j * 4;
        const float4* hr  = (const float4*)s_h[p] + j * 4;
        float a = 0.0f;
        #pragma unroll
        for (int i = 0; i < 4; i++) {
            float4 w = __ldg(w2r + i);
            float4 hh = hr[i];
            a += w.x * hh.x + w.y * hh.y + w.z * hh.z + w.w * hh.w;
        }
        a += __shfl_down_sync(0xffffffffu, a, 4, 8);
        a += __shfl_down_sync(0xffffffffu, a, 2, 8);
        a += __shfl_down_sync(0xffffffffu, a, 1, 8);
        if (j == 0) {
            const int pt = blockIdx.x * 4 + p;
            a += __ldg(b2 + oo);
            int d = oo & 1;
            float scale = (d == 0) ? (2.0f / (WW - 1)) : (2.0f / (HH - 1));
            float base  = __ldg(kp + pt * 2 + d);
            g_grid[pt * (2 * NP) + oo] = base + a * scale;
        }
    }
}

// ───────────── K2: resample from windows (1088 blocks x 256) ─────────────
__global__ __launch_bounds__(256)
void k2_sample(const float* __restrict__ feat, const float* __restrict__ kp,
               float* __restrict__ out)
{
    const int pt = blockIdx.x;
    const int c  = threadIdx.x;
    const int b  = pt / JJ;

    const float gx = __ldg(kp + pt * 2 + 0);
    const float gy = __ldg(kp + pt * 2 + 1);
    Geom g = make_geom(gx, gy);

    const size_t wi = (size_t)pt * CH + c;
    float4 q0 = g_win4[wi * 2 + 0];
    float4 q1 = g_win4[wi * 2 + 1];
    float2 ee = g_wine[wi];
    const int ilim = g.have_e ? 4 : 3;

    const float* plane = feat + ((size_t)b * CH + c) * (HH * WW);
    float* obase = out + (size_t)pt * (NP * CH) + c;

    #pragma unroll
    for (int n = 0; n < NP; n++) {
        float dgx = __ldg(&g_grid[pt * (2 * NP) + n * 2 + 0]);
        float dgy = __ldg(&g_grid[pt * (2 * NP) + n * 2 + 1]);

        float xx = (dgx + 1.0f) * 0.5f * (float)(WW - 1);
        float yy = (dgy + 1.0f) * 0.5f * (float)(HH - 1);
        float xf = floorf(xx), yf = floorf(yy);
        float ax1 = xx - xf, ax0 = 1.0f - ax1;
        float ay1 = yy - yf, ay0 = 1.0f - ay1;
        int dx0 = (int)xf, dy0 = (int)yf;
        int dx1 = dx0 + 1, dy1 = dy0 + 1;

        float ux0 = (dx0 >= 0 && dx0 <= WW - 1) ? 1.0f : 0.0f;
        float ux1 = (dx1 >= 0 && dx1 <= WW - 1) ? 1.0f : 0.0f;
        float uy0 = (dy0 >= 0 && dy0 <= HH - 1) ? 1.0f : 0.0f;
        float uy1 = (dy1 >= 0 && dy1 <= HH - 1) ? 1.0f : 0.0f;

        int cx0 = min(max(dx0, 0), WW - 1);
        int cx1 = min(max(dx1, 0), WW - 1);
        int cy0 = min(max(dy0, 0), HH - 1);
        int cy1 = min(max(dy1, 0), HH - 1);

        int i0 = cx0 - g.bc;
        int i1 = cx1 - g.bc;
        bool fast = (cy0 == g.yc0 || cy0 == g.yc1)
                 && (cy1 == g.yc0 || cy1 == g.yc1)
                 && (i0 >= 0) && (i1 <= ilim);

        float r;
        if (fast) {
            float4 ra = (cy0 == g.yc0) ? q0 : q1;
            float4 rb = (cy1 == g.yc0) ? q0 : q1;
            float ea  = (cy0 == g.yc0) ? ee.x : ee.y;
            float eb  = (cy1 == g.yc0) ? ee.x : ee.y;
            float v00 = pick5(ra, ea, i0);
            float v01 = pick5(ra, ea, i1);
            float v10 = pick5(rb, eb, i0);
            float v11 = pick5(rb, eb, i1);
            r = v00 * (ax0 * ay0 * ux0 * uy0)
              + v01 * (ax1 * ay0 * ux1 * uy0)
              + v10 * (ax0 * ay1 * ux0 * uy1)
              + v11 * (ax1 * ay1 * ux1 * uy1);
        } else {
            r = sample_bilinear_c(plane, dgx, dgy);
        }
        obase[n * CH] = r;
    }
}

extern "C" void kernel_launch(void* const* d_in, const int* in_sizes, int n_in,
                              void* d_out, int out_size)
{
    const float* feat = (const float*)d_in[0];   // [64,256,64,64]
    const float* kp   = (const float*)d_in[1];   // [64,17,2]
    const float* w1   = (const float*)d_in[2];   // [128,256]
    const float* b1   = (const float*)d_in[3];   // [128]
    const float* w2   = (const float*)d_in[4];   // [8,128]
    const float* b2   = (const float*)d_in[5];   // [8]
    float* out = (float*)d_out;                  // [64,17,1024]

    k0_win<<<NPTS / 2, 256>>>(feat, kp);
    k1_mlp<<<NPTS / 4, 256>>>(kp, w1, b1, w2, b2);
    k2_sample<<<NPTS, 256>>>(feat, kp, out);
}

// round 6
// speedup vs baseline: 1.5870x; 1.0010x over previous
#include <cuda_runtime.h>
#include <cuda_bf16.h>

#define BT 64
#define CH 256
#define HH 64
#define WW 64
#define JJ 17
#define NP 4
#define NPTS (BT * JJ)

// Scratch
__device__ float4 g_win4[NPTS * CH * 2];  // [pt][c][row0,row1]
__device__ float2 g_wine[NPTS * CH];      // [pt][c][e0,e1]
__device__ float4 g_seed4[NPTS * CH / 4]; // [pt][c] seed features (float4-aligned)
__device__ float  g_grid[NPTS * 2 * NP];  // [pt][n*2+d]

struct Geom {
    int yc0, yc1, bc, o0, o1;
    bool have_e;                 // edge column (bc+4) exists
    float w00, w01, w10, w11;
};

__device__ __forceinline__ Geom make_geom(float gx, float gy) {
    Geom g;
    float x = (gx + 1.0f) * 0.5f * (float)(WW - 1);
    float y = (gy + 1.0f) * 0.5f * (float)(HH - 1);
    float x0f = floorf(x), y0f = floorf(y);
    float wx1 = x - x0f, wx0 = 1.0f - wx1;
    float wy1 = y - y0f, wy0 = 1.0f - wy1;
    int x0 = (int)x0f, y0 = (int)y0f;
    int x1 = x0 + 1,   y1 = y0 + 1;
    float vx0 = (x0 >= 0 && x0 <= WW - 1) ? 1.0f : 0.0f;
    float vx1 = (x1 >= 0 && x1 <= WW - 1) ? 1.0f : 0.0f;
    float vy0 = (y0 >= 0 && y0 <= HH - 1) ? 1.0f : 0.0f;
    float vy1 = (y1 >= 0 && y1 <= HH - 1) ? 1.0f : 0.0f;
    int xc0 = min(max(x0, 0), WW - 1);
    int xc1 = min(max(x1, 0), WW - 1);
    g.yc0 = min(max(y0, 0), HH - 1);
    g.yc1 = min(max(y1, 0), HH - 1);
    g.bc  = xc0 & ~3;
    g.o0  = xc0 - g.bc;
    g.o1  = xc1 - g.bc;
    g.have_e = (g.bc < 60);
    g.w00 = wx0 * wy0 * vx0 * vy0;
    g.w01 = wx1 * wy0 * vx1 * vy0;
    g.w10 = wx0 * wy1 * vx0 * vy1;
    g.w11 = wx1 * wy1 * vx1 * vy1;
    return g;
}

__device__ __forceinline__ float sel4(float4 q, int i) {
    float r = q.x;
    if (i == 1) r = q.y;
    else if (i == 2) r = q.z;
    else if (i == 3) r = q.w;
    return r;
}
__device__ __forceinline__ float pick5(float4 q, float e, int i) {
    return (i == 4) ? e : sel4(q, i);
}

__device__ __forceinline__ float sample_bilinear_c(
    const float* __restrict__ plane, float gx, float gy)
{
    float x = (gx + 1.0f) * 0.5f * (float)(WW - 1);
    float y = (gy + 1.0f) * 0.5f * (float)(HH - 1);
    float x0f = floorf(x), y0f = floorf(y);
    float wx1 = x - x0f, wx0 = 1.0f - wx1;
    float wy1 = y - y0f, wy0 = 1.0f - wy1;
    int x0 = (int)x0f, y0 = (int)y0f;
    int x1 = x0 + 1,   y1 = y0 + 1;
    float vx0 = (x0 >= 0 && x0 <= WW - 1) ? 1.0f : 0.0f;
    float vx1 = (x1 >= 0 && x1 <= WW - 1) ? 1.0f : 0.0f;
    float vy0 = (y0 >= 0 && y0 <= HH - 1) ? 1.0f : 0.0f;
    float vy1 = (y1 >= 0 && y1 <= HH - 1) ? 1.0f : 0.0f;
    int xc0 = min(max(x0, 0), WW - 1);
    int xc1 = min(max(x1, 0), WW - 1);
    int yc0 = min(max(y0, 0), HH - 1);
    int yc1 = min(max(y1, 0), HH - 1);
    const float* r0 = plane + yc0 * WW;
    const float* r1 = plane + yc1 * WW;
    float v00 = __ldg(r0 + xc0);
    float v01 = __ldg(r0 + xc1);
    float v10 = __ldg(r1 + xc0);
    float v11 = __ldg(r1 + xc1);
    return v00 * (wx0 * wy0 * vx0 * vy0)
         + v01 * (wx1 * wy0 * vx1 * vy0)
         + v10 * (wx0 * wy1 * vx0 * vy1)
         + v11 * (wx1 * wy1 * vx1 * vy1);
}

// ───────────── K0: window gather + seed (544 blocks x 256), MLP-batched ─────────────
__global__ __launch_bounds__(256)
void k0_win(const float* __restrict__ feat, const float* __restrict__ kp)
{
    const int c   = threadIdx.x;
    const int pt0 = blockIdx.x * 2;
    const int pt1 = pt0 + 1;

    // geometry for both points (block-uniform)
    const float gxa = __ldg(kp + pt0 * 2 + 0), gya = __ldg(kp + pt0 * 2 + 1);
    const float gxb = __ldg(kp + pt1 * 2 + 0), gyb = __ldg(kp + pt1 * 2 + 1);
    Geom ga = make_geom(gxa, gya);
    Geom gb = make_geom(gxb, gyb);

    const float* pa = feat + ((size_t)(pt0 / JJ) * CH + c) * (HH * WW);
    const float* pb = feat + ((size_t)(pt1 / JJ) * CH + c) * (HH * WW);
    const float* ra0 = pa + ga.yc0 * WW;
    const float* ra1 = pa + ga.yc1 * WW;
    const float* rb0 = pb + gb.yc0 * WW;
    const float* rb1 = pb + gb.yc1 * WW;
    const int eia = min(ga.bc + 4, WW - 1);
    const int eib = min(gb.bc + 4, WW - 1);

    // front-load all 8 loads (no stores/branches in between)
    float4 qa0 = __ldg((const float4*)(ra0 + ga.bc));
    float4 qa1 = __ldg((const float4*)(ra1 + ga.bc));
    float4 qb0 = __ldg((const float4*)(rb0 + gb.bc));
    float4 qb1 = __ldg((const float4*)(rb1 + gb.bc));
    float  ea0 = __ldg(ra0 + eia);
    float  ea1 = __ldg(ra1 + eia);
    float  eb0 = __ldg(rb0 + eib);
    float  eb1 = __ldg(rb1 + eib);

    // seeds
    float sa = sel4(qa0, ga.o0) * ga.w00 + pick5(qa0, ea0, ga.o1) * ga.w01
             + sel4(qa1, ga.o0) * ga.w10 + pick5(qa1, ea1, ga.o1) * ga.w11;
    float sb = sel4(qb0, gb.o0) * gb.w00 + pick5(qb0, eb0, gb.o1) * gb.w01
             + sel4(qb1, gb.o0) * gb.w10 + pick5(qb1, eb1, gb.o1) * gb.w11;

    // stores (coalesced)
    const size_t wa = (size_t)pt0 * CH + c;
    const size_t wb = (size_t)pt1 * CH + c;
    g_win4[wa * 2 + 0] = qa0;
    g_win4[wa * 2 + 1] = qa1;
    g_win4[wb * 2 + 0] = qb0;
    g_win4[wb * 2 + 1] = qb1;
    g_wine[wa] = make_float2(ea0, ea1);
    g_wine[wb] = make_float2(eb0, eb1);
    ((float*)g_seed4)[wa] = sa;
    ((float*)g_seed4)[wb] = sb;
}

// ───────────── K1: MLP via smem-staged w1 GEMM (136 blocks x 256, 8 pts) ─────────────
#define KT 64
__global__ __launch_bounds__(256)
void k1_mlp(const float* __restrict__ kp,
            const float* __restrict__ w1, const float* __restrict__ b1,
            const float* __restrict__ w2, const float* __restrict__ b2)
{
    __shared__ float s_w1t[KT][129];                 // 33 KB, transposed tile
    __shared__ __align__(16) float s_seed[8][CH];    // 8 KB
    __shared__ float s_part[2][128][9];              // 9 KB (padded)
    __shared__ __align__(16) float s_h[8][128];      // 4 KB

    const int tid = threadIdx.x;
    const int p0  = blockIdx.x * 8;

    // load seeds (coalesced float4)
    {
        const float4* src = g_seed4 + (size_t)p0 * (CH / 4);
        #pragma unroll
        for (int j = 0; j < 2; j++) {
            int idx = tid + j * 256;        // 0..511
            int p   = idx >> 6;
            int k4  = idx & 63;
            *((float4*)&s_seed[p][k4 * 4]) = __ldg(src + idx);
        }
    }

    // layer 1: 256->128 over 8 points
    const int o = tid & 127;
    const int h = tid >> 7;
    float acc[8] = {0,0,0,0,0,0,0,0};

    for (int t = 0; t < CH / KT; t++) {
        __syncthreads();
        #pragma unroll
        for (int j = 0; j < 8; j++) {
            int L  = tid + j * 256;
            int oo = L >> 4;
            int k4 = L & 15;
            float4 v = __ldg((const float4*)(w1 + oo * CH + t * KT) + k4);
            s_w1t[k4 * 4 + 0][oo] = v.x;
            s_w1t[k4 * 4 + 1][oo] = v.y;
            s_w1t[k4 * 4 + 2][oo] = v.z;
            s_w1t[k4 * 4 + 3][oo] = v.w;
        }
        __syncthreads();

        #pragma unroll
        for (int kb = 0; kb < 4; kb++) {
            float wv[8];
            #pragma unroll
            for (int u = 0; u < 8; u++)
                wv[u] = s_w1t[h * 32 + kb * 8 + u][o];
            const int ch = t * KT + h * 32 + kb * 8;
            #pragma unroll
            for (int p = 0; p < 8; p++) {
                float4 s0 = *(const float4*)&s_seed[p][ch];
                float4 s1 = *(const float4*)&s_seed[p][ch + 4];
                acc[p] += wv[0] * s0.x + wv[1] * s0.y + wv[2] * s0.z + wv[3] * s0.w
                        + wv[4] * s1.x + wv[5] * s1.y + wv[6] * s1.z + wv[7] * s1.w;
            }
        }
    }
    #pragma unroll
    for (int p = 0; p < 8; p++) s_part[h][o][p] = acc[p];
    __syncthreads();

    if (tid < 128) {
        float bias = __ldg(b1 + tid);
        #pragma unroll
        for (int p = 0; p < 8; p++)
            s_h[p][tid] = fmaxf(s_part[0][tid][p] + s_part[1][tid][p] + bias, 0.0f);
    }
    __syncthreads();

    // layer 2: 8 pts x 8 outputs x 4 k-slices = 256 threads
    {
        const int p  = tid >> 5;
        const int r  = tid & 31;
        const int oo = r >> 2;
        const int j  = r & 3;
        const float4* w2r = (const float4*)w2 + oo * 32 + j * 8;
        const float4* hr  = (const float4*)s_h[p] + j * 8;
        float a = 0.0f;
        #pragma unroll
        for (int i = 0; i < 8; i++) {
            float4 w = __ldg(w2r + i);
            float4 hh = hr[i];
            a += w.x * hh.x + w.y * hh.y + w.z * hh.z + w.w * hh.w;
        }
        a += __shfl_down_sync(0xffffffffu, a, 2, 4);
        a += __shfl_down_sync(0xffffffffu, a, 1, 4);
        if (j == 0) {
            const int pt = p0 + p;
            a += __ldg(b2 + oo);
            int d = oo & 1;
            float scale = (d == 0) ? (2.0f / (WW - 1)) : (2.0f / (HH - 1));
            float base  = __ldg(kp + pt * 2 + d);
            g_grid[pt * (2 * NP) + oo] = base + a * scale;
        }
    }
}

// ───────────── K2: resample from windows (1088 blocks x 256) ─────────────
__global__ __launch_bounds__(256)
void k2_sample(const float* __restrict__ feat, const float* __restrict__ kp,
               float* __restrict__ out)
{
    const int pt = blockIdx.x;
    const int c  = threadIdx.x;
    const int b  = pt / JJ;

    const float gx = __ldg(kp + pt * 2 + 0);
    const float gy = __ldg(kp + pt * 2 + 1);
    Geom g = make_geom(gx, gy);

    const size_t wi = (size_t)pt * CH + c;
    float4 q0 = g_win4[wi * 2 + 0];
    float4 q1 = g_win4[wi * 2 + 1];
    float2 ee = g_wine[wi];
    const int ilim = g.have_e ? 4 : 3;

    const float* plane = feat + ((size_t)b * CH + c) * (HH * WW);
    float* obase = out + (size_t)pt * (NP * CH) + c;

    #pragma unroll
    for (int n = 0; n < NP; n++) {
        float dgx = __ldg(&g_grid[pt * (2 * NP) + n * 2 + 0]);
        float dgy = __ldg(&g_grid[pt * (2 * NP) + n * 2 + 1]);

        float xx = (dgx + 1.0f) * 0.5f * (float)(WW - 1);
        float yy = (dgy + 1.0f) * 0.5f * (float)(HH - 1);
        float xf = floorf(xx), yf = floorf(yy);
        float ax1 = xx - xf, ax0 = 1.0f - ax1;
        float ay1 = yy - yf, ay0 = 1.0f - ay1;
        int dx0 = (int)xf, dy0 = (int)yf;
        int dx1 = dx0 + 1, dy1 = dy0 + 1;

        float ux0 = (dx0 >= 0 && dx0 <= WW - 1) ? 1.0f : 0.0f;
        float ux1 = (dx1 >= 0 && dx1 <= WW - 1) ? 1.0f : 0.0f;
        float uy0 = (dy0 >= 0 && dy0 <= HH - 1) ? 1.0f : 0.0f;
        float uy1 = (dy1 >= 0 && dy1 <= HH - 1) ? 1.0f : 0.0f;

        int cx0 = min(max(dx0, 0), WW - 1);
        int cx1 = min(max(dx1, 0), WW - 1);
        int cy0 = min(max(dy0, 0), HH - 1);
        int cy1 = min(max(dy1, 0), HH - 1);

        int i0 = cx0 - g.bc;
        int i1 = cx1 - g.bc;
        bool fast = (cy0 == g.yc0 || cy0 == g.yc1)
                 && (cy1 == g.yc0 || cy1 == g.yc1)
                 && (i0 >= 0) && (i1 <= ilim);

        float r;
        if (fast) {
            float4 ra = (cy0 == g.yc0) ? q0 : q1;
            float4 rb = (cy1 == g.yc0) ? q0 : q1;
            float ea  = (cy0 == g.yc0) ? ee.x : ee.y;
            float eb  = (cy1 == g.yc0) ? ee.x : ee.y;
            float v00 = pick5(ra, ea, i0);
            float v01 = pick5(ra, ea, i1);
            float v10 = pick5(rb, eb, i0);
            float v11 = pick5(rb, eb, i1);
            r = v00 * (ax0 * ay0 * ux0 * uy0)
              + v01 * (ax1 * ay0 * ux1 * uy0)
              + v10 * (ax0 * ay1 * ux0 * uy1)
              + v11 * (ax1 * ay1 * ux1 * uy1);
        } else {
            r = sample_bilinear_c(plane, dgx, dgy);
        }
        obase[n * CH] = r;
    }
}

extern "C" void kernel_launch(void* const* d_in, const int* in_sizes, int n_in,
                              void* d_out, int out_size)
{
    const float* feat = (const float*)d_in[0];   // [64,256,64,64]
    const float* kp   = (const float*)d_in[1];   // [64,17,2]
    const float* w1   = (const float*)d_in[2];   // [128,256]
    const float* b1   = (const float*)d_in[3];   // [128]
    const float* w2   = (const float*)d_in[4];   // [8,128]
    const float* b2   = (const float*)d_in[5];   // [8]
    float* out = (float*)d_out;                  // [64,17,1024]

    k0_win<<<NPTS / 2, 256>>>(feat, kp);
    k1_mlp<<<NPTS / 8, 256>>>(kp, w1, b1, w2, b2);
    k2_sample<<<NPTS, 256>>>(feat, kp, out);
}

// round 8
// speedup vs baseline: 1.8396x; 1.1592x over previous
#include <cuda_runtime.h>
#include <cuda_bf16.h>

#define BT 64
#define CH 256
#define HH 64
#define WW 64
#define JJ 17
#define NP 4
#define NPTS (BT * JJ)

// Scratch
__device__ float4 g_corner[NPTS * CH];    // [pt][c] raw corner values (v00,v01,v10,v11)
__device__ float4 g_seed4[NPTS * CH / 4]; // [pt][c] seed features
__device__ float  g_grid[NPTS * 2 * NP];  // [pt][n*2+d]

struct Geom {
    int x0, y0;                  // unclamped cell indices
    int yc0, yc1, bc, o0, o1;
    bool have_e;
    float w00, w01, w10, w11;
};

__device__ __forceinline__ Geom make_geom(float gx, float gy) {
    Geom g;
    float x = (gx + 1.0f) * 0.5f * (float)(WW - 1);
    float y = (gy + 1.0f) * 0.5f * (float)(HH - 1);
    float x0f = floorf(x), y0f = floorf(y);
    float wx1 = x - x0f, wx0 = 1.0f - wx1;
    float wy1 = y - y0f, wy0 = 1.0f - wy1;
    g.x0 = (int)x0f; g.y0 = (int)y0f;
    int x0 = g.x0, y0 = g.y0;
    int x1 = x0 + 1, y1 = y0 + 1;
    float vx0 = (x0 >= 0 && x0 <= WW - 1) ? 1.0f : 0.0f;
    float vx1 = (x1 >= 0 && x1 <= WW - 1) ? 1.0f : 0.0f;
    float vy0 = (y0 >= 0 && y0 <= HH - 1) ? 1.0f : 0.0f;
    float vy1 = (y1 >= 0 && y1 <= HH - 1) ? 1.0f : 0.0f;
    int xc0 = min(max(x0, 0), WW - 1);
    int xc1 = min(max(x1, 0), WW - 1);
    g.yc0 = min(max(y0, 0), HH - 1);
    g.yc1 = min(max(y1, 0), HH - 1);
    g.bc  = xc0 & ~3;
    g.o0  = xc0 - g.bc;
    g.o1  = xc1 - g.bc;
    g.have_e = (g.o1 == 4);
    g.w00 = wx0 * wy0 * vx0 * vy0;
    g.w01 = wx1 * wy0 * vx1 * vy0;
    g.w10 = wx0 * wy1 * vx0 * vy1;
    g.w11 = wx1 * wy1 * vx1 * vy1;
    return g;
}

__device__ __forceinline__ float sel4(float4 q, int i) {
    float r = q.x;
    if (i == 1) r = q.y;
    else if (i == 2) r = q.z;
    else if (i == 3) r = q.w;
    return r;
}
__device__ __forceinline__ float pick5(float4 q, float e, int i) {
    return (i == 4) ? e : sel4(q, i);
}

// Full gather fallback (feat lines are L2-resident after k0)
__device__ __forceinline__ float sample_bilinear_c(
    const float* __restrict__ plane, float gx, float gy)
{
    float x = (gx + 1.0f) * 0.5f * (float)(WW - 1);
    float y = (gy + 1.0f) * 0.5f * (float)(HH - 1);
    float x0f = floorf(x), y0f = floorf(y);
    float wx1 = x - x0f, wx0 = 1.0f - wx1;
    float wy1 = y - y0f, wy0 = 1.0f - wy1;
    int x0 = (int)x0f, y0 = (int)y0f;
    int x1 = x0 + 1,   y1 = y0 + 1;
    float vx0 = (x0 >= 0 && x0 <= WW - 1) ? 1.0f : 0.0f;
    float vx1 = (x1 >= 0 && x1 <= WW - 1) ? 1.0f : 0.0f;
    float vy0 = (y0 >= 0 && y0 <= HH - 1) ? 1.0f : 0.0f;
    float vy1 = (y1 >= 0 && y1 <= HH - 1) ? 1.0f : 0.0f;
    int xc0 = min(max(x0, 0), WW - 1);
    int xc1 = min(max(x1, 0), WW - 1);
    int yc0 = min(max(y0, 0), HH - 1);
    int yc1 = min(max(y1, 0), HH - 1);
    const float* r0 = plane + yc0 * WW;
    const float* r1 = plane + yc1 * WW;
    float v00 = __ldg(r0 + xc0);
    float v01 = __ldg(r0 + xc1);
    float v10 = __ldg(r1 + xc0);
    float v11 = __ldg(r1 + xc1);
    return v00 * (wx0 * wy0 * vx0 * vy0)
         + v01 * (wx1 * wy0 * vx1 * vy0)
         + v10 * (wx0 * wy1 * vx0 * vy1)
         + v11 * (wx1 * wy1 * vx1 * vy1);
}

// ───────────── K0: corner gather + seed (1088 blocks x 256) ─────────────
__global__ __launch_bounds__(256)
void k0_win(const float* __restrict__ feat, const float* __restrict__ kp)
{
    const int pt = blockIdx.x;
    const int c  = threadIdx.x;
    const int b  = pt / JJ;

    const float gx = __ldg(kp + pt * 2 + 0);
    const float gy = __ldg(kp + pt * 2 + 1);
    Geom g = make_geom(gx, gy);

    const float* plane = feat + ((size_t)b * CH + c) * (HH * WW);
    const float* r0 = plane + g.yc0 * WW;
    const float* r1 = plane + g.yc1 * WW;

    float4 q0 = __ldg((const float4*)(r0 + g.bc));
    float4 q1 = __ldg((const float4*)(r1 + g.bc));
    float e0 = 0.0f, e1 = 0.0f;
    if (g.have_e) {                        // block-uniform, ~25% of blocks
        e0 = __ldg(r0 + g.bc + 4);
        e1 = __ldg(r1 + g.bc + 4);
    }

    // raw corner values (validity applied via weights)
    float v00 = sel4(q0, g.o0);
    float v01 = pick5(q0, e0, g.o1);
    float v10 = sel4(q1, g.o0);
    float v11 = pick5(q1, e1, g.o1);

    const size_t wi = (size_t)pt * CH + c;
    g_corner[wi] = make_float4(v00, v01, v10, v11);
    ((float*)g_seed4)[wi] = v00 * g.w00 + v01 * g.w01 + v10 * g.w10 + v11 * g.w11;
}

// ───────────── K1: MLP via smem-staged w1 GEMM (136 blocks x 256, 8 pts) ─────────────
#define KT 64
__global__ __launch_bounds__(256)
void k1_mlp(const float* __restrict__ kp,
            const float* __restrict__ w1, const float* __restrict__ b1,
            const float* __restrict__ w2, const float* __restrict__ b2)
{
    __shared__ float s_w1t[KT][129];
    __shared__ __align__(16) float s_seed[8][CH];
    __shared__ float s_part[2][128][9];
    __shared__ __align__(16) float s_h[8][128];

    const int tid = threadIdx.x;
    const int p0  = blockIdx.x * 8;

    // seeds (coalesced float4)
    {
        const float4* src = g_seed4 + (size_t)p0 * (CH / 4);
        #pragma unroll
        for (int j = 0; j < 2; j++) {
            int idx = tid + j * 256;
            int p   = idx >> 6;
            int k4  = idx & 63;
            *((float4*)&s_seed[p][k4 * 4]) = __ldg(src + idx);
        }
    }

    const int o = tid & 127;
    const int h = tid >> 7;
    float acc[8] = {0,0,0,0,0,0,0,0};

    for (int t = 0; t < CH / KT; t++) {
        __syncthreads();
        #pragma unroll
        for (int j = 0; j < 8; j++) {
            int L  = tid + j * 256;
            int oo = L >> 4;
            int k4 = L & 15;
            float4 v = __ldg((const float4*)(w1 + oo * CH + t * KT) + k4);
            s_w1t[k4 * 4 + 0][oo] = v.x;
            s_w1t[k4 * 4 + 1][oo] = v.y;
            s_w1t[k4 * 4 + 2][oo] = v.z;
            s_w1t[k4 * 4 + 3][oo] = v.w;
        }
        __syncthreads();

        #pragma unroll
        for (int kb = 0; kb < 4; kb++) {
            float wv[8];
            #pragma unroll
            for (int u = 0; u < 8; u++)
                wv[u] = s_w1t[h * 32 + kb * 8 + u][o];
            const int ch = t * KT + h * 32 + kb * 8;
            #pragma unroll
            for (int p = 0; p < 8; p++) {
                float4 s0 = *(const float4*)&s_seed[p][ch];
                float4 s1 = *(const float4*)&s_seed[p][ch + 4];
                acc[p] += wv[0] * s0.x + wv[1] * s0.y + wv[2] * s0.z + wv[3] * s0.w
                        + wv[4] * s1.x + wv[5] * s1.y + wv[6] * s1.z + wv[7] * s1.w;
            }
        }
    }
    #pragma unroll
    for (int p = 0; p < 8; p++) s_part[h][o][p] = acc[p];
    __syncthreads();

    if (tid < 128) {
        float bias = __ldg(b1 + tid);
        #pragma unroll
        for (int p = 0; p < 8; p++)
            s_h[p][tid] = fmaxf(s_part[0][tid][p] + s_part[1][tid][p] + bias, 0.0f);
    }
    __syncthreads();

    {
        const int p  = tid >> 5;
        const int r  = tid & 31;
        const int oo = r >> 2;
        const int j  = r & 3;
        const float4* w2r = (const float4*)w2 + oo * 32 + j * 8;
        const float4* hr  = (const float4*)s_h[p] + j * 8;
        float a = 0.0f;
        #pragma unroll
        for (int i = 0; i < 8; i++) {
            float4 w = __ldg(w2r + i);
            float4 hh = hr[i];
            a += w.x * hh.x + w.y * hh.y + w.z * hh.z + w.w * hh.w;
        }
        a += __shfl_down_sync(0xffffffffu, a, 2, 4);
        a += __shfl_down_sync(0xffffffffu, a, 1, 4);
        if (j == 0) {
            const int pt = p0 + p;
            a += __ldg(b2 + oo);
            int d = oo & 1;
            float scale = (d == 0) ? (2.0f / (WW - 1)) : (2.0f / (HH - 1));
            float base  = __ldg(kp + pt * 2 + d);
            g_grid[pt * (2 * NP) + oo] = base + a * scale;
        }
    }
}

// ───────────── K2: resample from corner quads (1088 blocks x 256) ─────────────
__global__ __launch_bounds__(256)
void k2_sample(const float* __restrict__ feat, const float* __restrict__ kp,
               float* __restrict__ out)
{
    const int pt = blockIdx.x;
    const int c  = threadIdx.x;
    const int b  = pt / JJ;

    const float gx = __ldg(kp + pt * 2 + 0);
    const float gy = __ldg(kp + pt * 2 + 1);
    Geom g = make_geom(gx, gy);

    const size_t wi = (size_t)pt * CH + c;
    float4 cv = g_corner[wi];
    const float* plane = feat + ((size_t)b * CH + c) * (HH * WW);
    float* obase = out + (size_t)pt * (NP * CH) + c;

    #pragma unroll
    for (int n = 0; n < NP; n++) {
        float dgx = __ldg(&g_grid[pt * (2 * NP) + n * 2 + 0]);
        float dgy = __ldg(&g_grid[pt * (2 * NP) + n * 2 + 1]);

        float xx = (dgx + 1.0f) * 0.5f * (float)(WW - 1);
        float yy = (dgy + 1.0f) * 0.5f * (float)(HH - 1);
        float xf = floorf(xx), yf = floorf(yy);
        float ax1 = xx - xf, ax0 = 1.0f - ax1;
        float ay1 = yy - yf, ay0 = 1.0f - ay1;
        int dx0 = (int)xf, dy0 = (int)yf;

        bool fast = (dx0 == g.x0) && (dy0 == g.y0);   // block-uniform

        float r;
        if (fast) {
            // same cell -> same clamped coords & validity structure as seed
            int dx1 = dx0 + 1, dy1 = dy0 + 1;
            float ux0 = (dx0 >= 0 && dx0 <= WW - 1) ? 1.0f : 0.0f;
            float ux1 = (dx1 >= 0 && dx1 <= WW - 1) ? 1.0f : 0.0f;
            float uy0 = (dy0 >= 0 && dy0 <= HH - 1) ? 1.0f : 0.0f;
            float uy1 = (dy1 >= 0 && dy1 <= HH - 1) ? 1.0f : 0.0f;
            r = cv.x * (ax0 * ay0 * ux0 * uy0)
              + cv.y * (ax1 * ay0 * ux1 * uy0)
              + cv.z * (ax0 * ay1 * ux0 * uy1)
              + cv.w * (ax1 * ay1 * ux1 * uy1);
        } else {
            r = sample_bilinear_c(plane, dgx, dgy);
        }
        obase[n * CH] = r;
    }
}

extern "C" void kernel_launch(void* const* d_in, const int* in_sizes, int n_in,
                              void* d_out, int out_size)
{
    const float* feat = (const float*)d_in[0];   // [64,256,64,64]
    const float* kp   = (const float*)d_in[1];   // [64,17,2]
    const float* w1   = (const float*)d_in[2];   // [128,256]
    const float* b1   = (const float*)d_in[3];   // [128]
    const float* w2   = (const float*)d_in[4];   // [8,128]
    const float* b2   = (const float*)d_in[5];   // [8]
    float* out = (float*)d_out;                  // [64,17,1024]

    k0_win<<<NPTS, 256>>>(feat, kp);
    k1_mlp<<<NPTS / 8, 256>>>(kp, w1, b1, w2, b2);
    k2_sample<<<NPTS, 256>>>(feat, kp, out);
}